// round 1
// baseline (speedup 1.0000x reference)
#include <cuda_runtime.h>
#include <cuda_bf16.h>

#define NMAX 524288
#define E 8
#define H 64
#define TPB 256

// ---- scratch (no allocations allowed) ----
__device__ int g_idx[NMAX];
__device__ int g_perm[NMAX];
__device__ int g_counts[E];
__device__ int g_base[E];
__device__ int g_cursor[E];

// ---- kernel 0: zero counters (graph replays must re-init) ----
__global__ void k_zero() {
    if (threadIdx.x < E) g_counts[threadIdx.x] = 0;
}

// ---- kernel 1: routing + per-block histogram ----
__global__ void k_route(const float* __restrict__ x, int n) {
    __shared__ int hist[E];
    if (threadIdx.x < E) hist[threadIdx.x] = 0;
    __syncthreads();
    int i = blockIdx.x * blockDim.x + threadIdx.x;
    if (i < n) {
        float x0 = x[3 * i + 0];
        float x1 = x[3 * i + 1];
        float x2 = x[3 * i + 2];
        float u0 = fminf(fmaxf((x0 + 1.0f) * 0.5f, 0.0f), 0.99f);
        float u1 = fminf(fmaxf((x1 + 1.0f) * 0.5f, 0.0f), 0.99f);
        float u2 = fminf(fmaxf((x2 + 1.0f) * 0.5f, 0.0f), 0.99f);
        int g0 = (int)(u0 * 2.0f);
        int g1 = (int)(u1 * 2.0f);
        int g2 = (int)(u2 * 2.0f);
        int idx = g0 + 2 * g1 + 4 * g2;
        g_idx[i] = idx;
        atomicAdd(&hist[idx], 1);
    }
    __syncthreads();
    if (threadIdx.x < E) atomicAdd(&g_counts[threadIdx.x], hist[threadIdx.x]);
}

// ---- kernel 2: exclusive prefix over 8 buckets ----
__global__ void k_prefix() {
    if (threadIdx.x == 0) {
        int s = 0;
        for (int e = 0; e < E; e++) {
            g_base[e] = s;
            g_cursor[e] = s;
            s += g_counts[e];
        }
    }
}

// ---- kernel 3: scatter point ids into expert-sorted order ----
__global__ void k_scatter(int n) {
    int i = blockIdx.x * blockDim.x + threadIdx.x;
    if (i < n) {
        int e = g_idx[i];
        int p = atomicAdd(&g_cursor[e], 1);
        g_perm[p] = i;
    }
}

// ---- kernel 4: per-expert fused MLP ----
// grid = E * blocks_per_e; block (e, j) handles sorted slots
// [base[e] + j*TPB, base[e] + (j+1)*TPB). Over-launched blocks exit fast.
__global__ void __launch_bounds__(TPB, 2)
k_mlp(const float* __restrict__ x,
      const float* __restrict__ emin_g, const float* __restrict__ emax_g,
      const float* __restrict__ W1g, const float* __restrict__ b1g,
      const float* __restrict__ W2g, const float* __restrict__ b2g,
      const float* __restrict__ W3g, const float* __restrict__ b3g,
      float* __restrict__ out, int blocks_per_e) {
    int e = blockIdx.x / blocks_per_e;
    int jb = blockIdx.x - e * blocks_per_e;
    int cnt = g_counts[e];
    int start = jb * TPB;
    if (start >= cnt) return;   // whole block exits before any sync

    __shared__ __align__(16) float sW1[3][H];
    __shared__ __align__(16) float sW2[H][H];
    __shared__ __align__(16) float sb1[H];
    __shared__ __align__(16) float sb2[H];
    __shared__ __align__(16) float sW3[H];
    __shared__ float sb3;
    __shared__ float sext[6];

    // cooperative weight load (broadcast-friendly smem layout, row-major [k][j])
    for (int t = threadIdx.x; t < 3 * H; t += TPB) sW1[t / H][t % H] = W1g[e * 3 * H + t];
    for (int t = threadIdx.x; t < H * H; t += TPB) sW2[t / H][t % H] = W2g[e * H * H + t];
    for (int t = threadIdx.x; t < H; t += TPB) {
        sb1[t] = b1g[e * H + t];
        sb2[t] = b2g[e * H + t];
        sW3[t] = W3g[e * H + t];
    }
    if (threadIdx.x == 0) sb3 = b3g[e];
    if (threadIdx.x < 3) {
        sext[threadIdx.x]     = emin_g[e * 3 + threadIdx.x];
        sext[threadIdx.x + 3] = emax_g[e * 3 + threadIdx.x];
    }
    __syncthreads();

    int slot = start + threadIdx.x;
    if (slot >= cnt) return;
    int p = g_perm[g_base[e] + slot];

    float x0 = x[3 * p + 0];
    float x1 = x[3 * p + 1];
    float x2 = x[3 * p + 2];
    float xn0 = -1.0f + 2.0f * (x0 - sext[0]) / (sext[3] - sext[0]);
    float xn1 = -1.0f + 2.0f * (x1 - sext[1]) / (sext[4] - sext[1]);
    float xn2 = -1.0f + 2.0f * (x2 - sext[2]) / (sext[5] - sext[2]);

    // layer 1: 3 -> 64, relu
    float h1[H];
#pragma unroll
    for (int k = 0; k < H; k++) {
        float a = sb1[k];
        a = fmaf(xn0, sW1[0][k], a);
        a = fmaf(xn1, sW1[1][k], a);
        a = fmaf(xn2, sW1[2][k], a);
        h1[k] = fmaxf(a, 0.0f);
    }

    // layer 2 + layer 3 fused: 64 -> 64 relu, dot with W3
    float oacc = sb3;
    for (int jj = 0; jj < H; jj += 4) {   // 16 dynamic iters (keep I$ small)
        float a0 = sb2[jj + 0];
        float a1 = sb2[jj + 1];
        float a2 = sb2[jj + 2];
        float a3 = sb2[jj + 3];
#pragma unroll
        for (int k = 0; k < H; k++) {
            float4 w = *(const float4*)&sW2[k][jj];
            float hk = h1[k];
            a0 = fmaf(hk, w.x, a0);
            a1 = fmaf(hk, w.y, a1);
            a2 = fmaf(hk, w.z, a2);
            a3 = fmaf(hk, w.w, a3);
        }
        oacc = fmaf(fmaxf(a0, 0.0f), sW3[jj + 0], oacc);
        oacc = fmaf(fmaxf(a1, 0.0f), sW3[jj + 1], oacc);
        oacc = fmaf(fmaxf(a2, 0.0f), sW3[jj + 2], oacc);
        oacc = fmaf(fmaxf(a3, 0.0f), sW3[jj + 3], oacc);
    }
    out[p] = oacc;
}

extern "C" void kernel_launch(void* const* d_in, const int* in_sizes, int n_in,
                              void* d_out, int out_size) {
    const float* x    = (const float*)d_in[0];
    const float* emin = (const float*)d_in[1];
    const float* emax = (const float*)d_in[2];
    const float* W1   = (const float*)d_in[3];
    const float* b1   = (const float*)d_in[4];
    const float* W2   = (const float*)d_in[5];
    const float* b2   = (const float*)d_in[6];
    const float* W3   = (const float*)d_in[7];
    const float* b3   = (const float*)d_in[8];
    float* out = (float*)d_out;

    int n = in_sizes[0] / 3;
    int nblk = (n + TPB - 1) / TPB;

    k_zero<<<1, 32>>>();
    k_route<<<nblk, TPB>>>(x, n);
    k_prefix<<<1, 32>>>();
    k_scatter<<<nblk, TPB>>>(n);
    k_mlp<<<E * nblk, TPB>>>(x, emin, emax, W1, b1, W2, b2, W3, b3, out, nblk);
}

// round 2
// speedup vs baseline: 1.5131x; 1.5131x over previous
#include <cuda_runtime.h>
#include <cuda_bf16.h>
#include <cstdint>

#define NMAX 524288
#define E 8
#define H 64
#define TPB 256
#define NBLKMAX (NMAX / TPB)

// ---- scratch (no allocations allowed) ----
__device__ int g_idx[NMAX];
__device__ int g_perm[NMAX];
__device__ int g_bh[NBLKMAX * E];
__device__ int g_counts[E];
__device__ int g_base[E];
__device__ int g_cursor[E];

// ---------- f32x2 helpers (FFMA2 only reachable via PTX) ----------
__device__ __forceinline__ void ffma2(uint64_t& d, uint64_t a, uint64_t b) {
    asm("fma.rn.f32x2 %0, %1, %2, %0;" : "+l"(d) : "l"(a), "l"(b));
}
__device__ __forceinline__ uint64_t pack2(float v) {
    uint64_t r;
    asm("mov.b64 %0, {%1, %1};" : "=l"(r) : "f"(v));
    return r;
}
__device__ __forceinline__ float2 unpack2(uint64_t v) {
    float2 f;
    asm("mov.b64 {%0, %1}, %2;" : "=f"(f.x), "=f"(f.y) : "l"(v));
    return f;
}

// ---- kernel 1: routing + per-block histogram (no global atomics) ----
__global__ void k_route(const float* __restrict__ x, int n) {
    __shared__ int hist[E];
    if (threadIdx.x < E) hist[threadIdx.x] = 0;
    __syncthreads();
    int i = blockIdx.x * TPB + threadIdx.x;
    if (i < n) {
        float x0 = x[3 * i + 0];
        float x1 = x[3 * i + 1];
        float x2 = x[3 * i + 2];
        float u0 = fminf(fmaxf((x0 + 1.0f) * 0.5f, 0.0f), 0.99f);
        float u1 = fminf(fmaxf((x1 + 1.0f) * 0.5f, 0.0f), 0.99f);
        float u2 = fminf(fmaxf((x2 + 1.0f) * 0.5f, 0.0f), 0.99f);
        int idx = (int)(u0 * 2.0f) + 2 * (int)(u1 * 2.0f) + 4 * (int)(u2 * 2.0f);
        g_idx[i] = idx;
        atomicAdd(&hist[idx], 1);
    }
    __syncthreads();
    if (threadIdx.x < E) g_bh[blockIdx.x * E + threadIdx.x] = hist[threadIdx.x];
}

// ---- kernel 2: totals + exclusive prefix over 8 buckets ----
__global__ void k_prefix(int nblk) {
    __shared__ int partial[256];
    int e = threadIdx.x % E;
    int c = threadIdx.x / E;      // 32 chunks per expert
    int s = 0;
    for (int b = c; b < nblk; b += 32) s += g_bh[b * E + e];
    partial[threadIdx.x] = s;
    __syncthreads();
    if (threadIdx.x == 0) {
        int base = 0;
        for (int ee = 0; ee < E; ee++) {
            int tot = 0;
            for (int cc = 0; cc < 32; cc++) tot += partial[cc * E + ee];
            g_counts[ee] = tot;
            g_base[ee]   = base;
            g_cursor[ee] = base;
            base += tot;
        }
    }
}

// ---- kernel 3: scatter (one global atomic per block per expert) ----
__global__ void k_scatter(int n) {
    __shared__ int hist[E], sbase[E], scur[E];
    int tid = threadIdx.x;
    if (tid < E) { hist[tid] = 0; scur[tid] = 0; }
    __syncthreads();
    int i = blockIdx.x * TPB + tid;
    int e = 0;
    if (i < n) {
        e = g_idx[i];
        atomicAdd(&hist[e], 1);
    }
    __syncthreads();
    if (tid < E) sbase[tid] = atomicAdd(&g_cursor[tid], hist[tid]);
    __syncthreads();
    if (i < n) {
        int r = atomicAdd(&scur[e], 1);
        g_perm[sbase[e] + r] = i;
    }
}

// ---- kernel 4: per-expert fused MLP with f32x2 packed FMA ----
__global__ void __launch_bounds__(TPB)
k_mlp(const float* __restrict__ x,
      const float* __restrict__ emin_g, const float* __restrict__ emax_g,
      const float* __restrict__ W1g, const float* __restrict__ b1g,
      const float* __restrict__ W2g, const float* __restrict__ b2g,
      const float* __restrict__ W3g, const float* __restrict__ b3g,
      float* __restrict__ out, int blocks_per_e) {
    int e  = blockIdx.x / blocks_per_e;
    int jb = blockIdx.x - e * blocks_per_e;
    int cnt = g_counts[e];
    int start = jb * TPB;
    if (start >= cnt) return;   // whole block exits before any sync

    __shared__ __align__(16) float sW1[3][H];
    __shared__ __align__(16) float sW2[H][H];
    __shared__ __align__(16) float sb1[H];
    __shared__ __align__(16) float sb2[H];
    __shared__ __align__(16) float sW3[H];
    __shared__ float sb3;
    __shared__ float sext[6];

    for (int t = threadIdx.x; t < 3 * H; t += TPB) sW1[t / H][t % H] = W1g[e * 3 * H + t];
    for (int t = threadIdx.x; t < H * H; t += TPB) sW2[t / H][t % H] = W2g[e * H * H + t];
    for (int t = threadIdx.x; t < H; t += TPB) {
        sb1[t] = b1g[e * H + t];
        sb2[t] = b2g[e * H + t];
        sW3[t] = W3g[e * H + t];
    }
    if (threadIdx.x == 0) sb3 = b3g[e];
    if (threadIdx.x < 3) {
        sext[threadIdx.x]     = emin_g[e * 3 + threadIdx.x];
        sext[threadIdx.x + 3] = emax_g[e * 3 + threadIdx.x];
    }
    __syncthreads();

    int slot = start + threadIdx.x;
    if (slot >= cnt) return;
    int p = g_perm[g_base[e] + slot];

    float x0 = x[3 * p + 0];
    float x1 = x[3 * p + 1];
    float x2 = x[3 * p + 2];
    float xn0 = -1.0f + 2.0f * (x0 - sext[0]) / (sext[3] - sext[0]);
    float xn1 = -1.0f + 2.0f * (x1 - sext[1]) / (sext[4] - sext[1]);
    float xn2 = -1.0f + 2.0f * (x2 - sext[2]) / (sext[5] - sext[2]);

    // layer 1: 3 -> 64, relu (broadcast smem reads)
    float h1[H];
#pragma unroll
    for (int k = 0; k < H; k++) {
        float a = sb1[k];
        a = fmaf(xn0, sW1[0][k], a);
        a = fmaf(xn1, sW1[1][k], a);
        a = fmaf(xn2, sW1[2][k], a);
        h1[k] = fmaxf(a, 0.0f);
    }

    // layer 2 (64->64, relu) + layer 3 (dot with W3), f32x2 packed.
    // 4 dynamic groups of 16 outputs; k fully unrolled so h1[] stays in regs.
    float oacc = sb3;
    for (int g = 0; g < 4; g++) {
        const int j0 = g * 16;
        uint64_t a[8];
        const uint64_t* binit = (const uint64_t*)&sb2[j0];
#pragma unroll
        for (int q = 0; q < 8; q++) a[q] = binit[q];

#pragma unroll
        for (int k = 0; k < H; k++) {
            uint64_t hk2 = pack2(h1[k]);
            const ulonglong2* wrow = (const ulonglong2*)&sW2[k][j0];
            ulonglong2 w0 = wrow[0];
            ulonglong2 w1 = wrow[1];
            ulonglong2 w2 = wrow[2];
            ulonglong2 w3 = wrow[3];
            ffma2(a[0], hk2, w0.x); ffma2(a[1], hk2, w0.y);
            ffma2(a[2], hk2, w1.x); ffma2(a[3], hk2, w1.y);
            ffma2(a[4], hk2, w2.x); ffma2(a[5], hk2, w2.y);
            ffma2(a[6], hk2, w3.x); ffma2(a[7], hk2, w3.y);
        }

#pragma unroll
        for (int q = 0; q < 8; q++) {
            float2 v = unpack2(a[q]);
            oacc = fmaf(fmaxf(v.x, 0.0f), sW3[j0 + 2 * q],     oacc);
            oacc = fmaf(fmaxf(v.y, 0.0f), sW3[j0 + 2 * q + 1], oacc);
        }
    }
    out[p] = oacc;
}

extern "C" void kernel_launch(void* const* d_in, const int* in_sizes, int n_in,
                              void* d_out, int out_size) {
    const float* x    = (const float*)d_in[0];
    const float* emin = (const float*)d_in[1];
    const float* emax = (const float*)d_in[2];
    const float* W1   = (const float*)d_in[3];
    const float* b1   = (const float*)d_in[4];
    const float* W2   = (const float*)d_in[5];
    const float* b2   = (const float*)d_in[6];
    const float* W3   = (const float*)d_in[7];
    const float* b3   = (const float*)d_in[8];
    float* out = (float*)d_out;

    int n = in_sizes[0] / 3;
    int nblk = (n + TPB - 1) / TPB;

    k_route<<<nblk, TPB>>>(x, n);
    k_prefix<<<1, 256>>>(nblk);
    k_scatter<<<nblk, TPB>>>(n);
    k_mlp<<<E * nblk, TPB>>>(x, emin, emax, W1, b1, W2, b2, W3, b3, out, nblk);
}

// round 4
// speedup vs baseline: 3.9731x; 2.6258x over previous
#include <cuda_runtime.h>
#include <cuda_bf16.h>
#include <cstdint>

#define NMAX 524288
#define E 8
#define H 64
#define TPB 256
#define MTPB 256
#define BPE 19
#define NBLKMAX (NMAX / TPB)

// ---- scratch ----
__device__ int g_idx[NMAX];
__device__ int g_perm[NMAX];
__device__ int g_bh[NBLKMAX * E];
__device__ int g_counts[E];
__device__ int g_base[E];
__device__ int g_cursor[E];

// ================= helpers =================
// pack two f32 -> bf16x2 word: low half = lo arg, high half = hi arg
__device__ __forceinline__ uint32_t packbf2(float lo, float hi) {
    uint32_t r;
    asm("cvt.rn.bf16x2.f32 %0, %1, %2;" : "=r"(r) : "f"(hi), "f"(lo));
    return r;
}
// bf16 element of packed word, as float (exact)
__device__ __forceinline__ float bflo_f(uint32_t w) { return __uint_as_float(w << 16); }
__device__ __forceinline__ float bfhi_f(uint32_t w) { return __uint_as_float(w & 0xffff0000u); }

__device__ __forceinline__ void mma16816(float* c, uint32_t a0, uint32_t a1,
                                         uint32_t a2, uint32_t a3,
                                         uint32_t b0, uint32_t b1) {
    asm volatile(
        "mma.sync.aligned.m16n8k16.row.col.f32.bf16.bf16.f32 "
        "{%0,%1,%2,%3}, {%4,%5,%6,%7}, {%8,%9}, {%0,%1,%2,%3};"
        : "+f"(c[0]), "+f"(c[1]), "+f"(c[2]), "+f"(c[3])
        : "r"(a0), "r"(a1), "r"(a2), "r"(a3), "r"(b0), "r"(b1));
}

// ================= sort kernels =================
__global__ void k_route(const float* __restrict__ x, int n) {
    __shared__ int hist[E];
    if (threadIdx.x < E) hist[threadIdx.x] = 0;
    __syncthreads();
    int i = blockIdx.x * TPB + threadIdx.x;
    if (i < n) {
        float u0 = fminf(fmaxf((x[3 * i + 0] + 1.0f) * 0.5f, 0.0f), 0.99f);
        float u1 = fminf(fmaxf((x[3 * i + 1] + 1.0f) * 0.5f, 0.0f), 0.99f);
        float u2 = fminf(fmaxf((x[3 * i + 2] + 1.0f) * 0.5f, 0.0f), 0.99f);
        int idx = (int)(u0 * 2.0f) + 2 * (int)(u1 * 2.0f) + 4 * (int)(u2 * 2.0f);
        g_idx[i] = idx;
        atomicAdd(&hist[idx], 1);
    }
    __syncthreads();
    if (threadIdx.x < E) g_bh[blockIdx.x * E + threadIdx.x] = hist[threadIdx.x];
}

__global__ void k_prefix(int nblk) {
    __shared__ int partial[256];
    int e = threadIdx.x % E;
    int c = threadIdx.x / E;
    int s = 0;
    for (int b = c; b < nblk; b += 32) s += g_bh[b * E + e];
    partial[threadIdx.x] = s;
    __syncthreads();
    if (threadIdx.x == 0) {
        int base = 0;
        for (int ee = 0; ee < E; ee++) {
            int tot = 0;
            for (int cc = 0; cc < 32; cc++) tot += partial[cc * E + ee];
            g_counts[ee] = tot;
            g_base[ee] = base;
            g_cursor[ee] = base;
            base += tot;
        }
    }
}

__global__ void k_scatter(int n) {
    __shared__ int hist[E], sbase[E], scur[E];
    int tid = threadIdx.x;
    if (tid < E) { hist[tid] = 0; scur[tid] = 0; }
    __syncthreads();
    int i = blockIdx.x * TPB + tid;
    int e = 0;
    if (i < n) {
        e = g_idx[i];
        atomicAdd(&hist[e], 1);
    }
    __syncthreads();
    if (tid < E) sbase[tid] = atomicAdd(&g_cursor[tid], hist[tid]);
    __syncthreads();
    if (i < n) {
        int r = atomicAdd(&scur[e], 1);
        g_perm[sbase[e] + r] = i;
    }
}

// ================= HMMA MLP =================
// Each warp: 32 points (M=32, 2 m-tiles), N=64 (8 n-tiles), K=64 (4 k-tiles),
// bf16 hi/lo 3-pass for fp32-grade precision.
__global__ void __launch_bounds__(MTPB)
k_mlp(const float* __restrict__ x,
      const float* __restrict__ emin_g, const float* __restrict__ emax_g,
      const float* __restrict__ W1g, const float* __restrict__ b1g,
      const float* __restrict__ W2g, const float* __restrict__ b2g,
      const float* __restrict__ W3g, const float* __restrict__ b3g,
      float* __restrict__ out) {
    __shared__ uint2 sB[2][4][8][32];   // [hi/lo][ktile][ntile][lane] = (b0,b1)
    __shared__ float sW1[3][H];
    __shared__ float sb1[H], sb2[H], sW3[H];
    __shared__ float sext[6];
    __shared__ float sb3v;

    const int tid = threadIdx.x;
    const int e  = blockIdx.x / BPE;
    const int jb = blockIdx.x % BPE;

    // ---- stage small weights ----
    for (int t = tid; t < 3 * H; t += MTPB) sW1[t / H][t % H] = W1g[e * 3 * H + t];
    for (int t = tid; t < H; t += MTPB) {
        sb1[t] = b1g[e * H + t];
        sb2[t] = b2g[e * H + t];
        sW3[t] = W3g[e * H + t];
    }
    if (tid < 3) {
        sext[tid]     = emin_g[e * 3 + tid];
        sext[tid + 3] = emax_g[e * 3 + tid];
    }
    if (tid == 0) sb3v = b3g[e];

    // ---- stage B fragments (W2 as bf16 hi/lo) in mma register order ----
    // B frag (k16 x n8), thread ln: b0 holds B[2*(ln%4)+{0,1}][ln/4], b1 = rows +8
    {
        const float* w2e = W2g + e * H * H;
        for (int it = 0; it < 4; it++) {
            int idx = tid + it * MTPB;     // 1024 entries: (kt, nt, lane)
            int kt = idx >> 8;
            int nt = (idx >> 5) & 7;
            int ln = idx & 31;
            int k0 = kt * 16 + 2 * (ln & 3);
            int n  = nt * 8 + (ln >> 2);
            float v00 = w2e[(k0)     * H + n];
            float v01 = w2e[(k0 + 1) * H + n];
            float v10 = w2e[(k0 + 8) * H + n];
            float v11 = w2e[(k0 + 9) * H + n];
            uint32_t h0 = packbf2(v00, v01);
            uint32_t h1 = packbf2(v10, v11);
            uint32_t l0 = packbf2(v00 - bflo_f(h0), v01 - bfhi_f(h0));
            uint32_t l1 = packbf2(v10 - bflo_f(h1), v11 - bfhi_f(h1));
            sB[0][kt][nt][ln] = make_uint2(h0, h1);
            sB[1][kt][nt][ln] = make_uint2(l0, l1);
        }
    }
    __syncthreads();

    const int lane = tid & 31;
    const int wid  = tid >> 5;
    const int c4 = lane & 3;      // n / k sub-index
    const int r4 = lane >> 2;     // row group
    const int cnt = g_counts[e];
    const int gb  = g_base[e];
    const float e0 = sext[0], e1 = sext[1], e2 = sext[2];
    const float f0 = sext[3], f1 = sext[4], f2 = sext[5];
    const float b3s = sb3v;

    for (int base = (jb * 8 + wid) * 32; base < cnt; base += BPE * 8 * 32) {
        int slot = base + lane;
        int p = g_perm[gb + min(slot, cnt - 1)];
        float xn0 = -1.0f + 2.0f * (x[3 * p + 0] - e0) / (f0 - e0);
        float xn1 = -1.0f + 2.0f * (x[3 * p + 1] - e1) / (f1 - e1);
        float xn2 = -1.0f + 2.0f * (x[3 * p + 2] - e2) / (f2 - e2);

        // coordinates of the 4 rows this thread's A fragments need
        float xr[4][3];
#pragma unroll
        for (int rs = 0; rs < 4; rs++) {
            int src = r4 + 8 * rs;
            xr[rs][0] = __shfl_sync(0xffffffffu, xn0, src);
            xr[rs][1] = __shfl_sync(0xffffffffu, xn1, src);
            xr[rs][2] = __shfl_sync(0xffffffffu, xn2, src);
        }

        float C[2][8][4];
#pragma unroll
        for (int mt = 0; mt < 2; mt++)
#pragma unroll
            for (int nt = 0; nt < 8; nt++)
#pragma unroll
                for (int q = 0; q < 4; q++) C[mt][nt][q] = 0.0f;

#pragma unroll
        for (int kt = 0; kt < 4; kt++) {
            int k0 = kt * 16 + 2 * c4;
            float2 b1L = *(const float2*)&sb1[k0];
            float2 b1H = *(const float2*)&sb1[k0 + 8];
            float2 wL0 = *(const float2*)&sW1[0][k0];
            float2 wL1 = *(const float2*)&sW1[1][k0];
            float2 wL2 = *(const float2*)&sW1[2][k0];
            float2 wH0 = *(const float2*)&sW1[0][k0 + 8];
            float2 wH1 = *(const float2*)&sW1[1][k0 + 8];
            float2 wH2 = *(const float2*)&sW1[2][k0 + 8];

            uint32_t ahi[2][4], alo[2][4];
#pragma unroll
            for (int rs = 0; rs < 4; rs++) {
                float a = xr[rs][0], b = xr[rs][1], c = xr[rs][2];
                float hx = fmaxf(fmaf(a, wL0.x, fmaf(b, wL1.x, fmaf(c, wL2.x, b1L.x))), 0.0f);
                float hy = fmaxf(fmaf(a, wL0.y, fmaf(b, wL1.y, fmaf(c, wL2.y, b1L.y))), 0.0f);
                float gx = fmaxf(fmaf(a, wH0.x, fmaf(b, wH1.x, fmaf(c, wH2.x, b1H.x))), 0.0f);
                float gy = fmaxf(fmaf(a, wH0.y, fmaf(b, wH1.y, fmaf(c, wH2.y, b1H.y))), 0.0f);
                uint32_t ph  = packbf2(hx, hy);
                uint32_t pg  = packbf2(gx, gy);
                uint32_t pl  = packbf2(hx - bflo_f(ph), hy - bfhi_f(ph));
                uint32_t pgl = packbf2(gx - bflo_f(pg), gy - bfhi_f(pg));
                int mt = rs >> 1, half = rs & 1;
                ahi[mt][half]     = ph;   // a0 / a1  (k low 8)
                ahi[mt][2 + half] = pg;   // a2 / a3  (k high 8)
                alo[mt][half]     = pl;
                alo[mt][2 + half] = pgl;
            }

#pragma unroll
            for (int nt = 0; nt < 8; nt++) {
                uint2 bh = sB[0][kt][nt][lane];
                uint2 bl = sB[1][kt][nt][lane];
#pragma unroll
                for (int mt = 0; mt < 2; mt++) {
                    mma16816(C[mt][nt], ahi[mt][0], ahi[mt][1], ahi[mt][2], ahi[mt][3], bh.x, bh.y);
                    mma16816(C[mt][nt], ahi[mt][0], ahi[mt][1], ahi[mt][2], ahi[mt][3], bl.x, bl.y);
                    mma16816(C[mt][nt], alo[mt][0], alo[mt][1], alo[mt][2], alo[mt][3], bh.x, bh.y);
                }
            }
        }

        // ---- epilogue: bias + relu + dot(W3), reduce across the 4-lane group ----
#pragma unroll
        for (int rs = 0; rs < 4; rs++) {
            int mt = rs >> 1, half = rs & 1;
            float acc = 0.0f;
#pragma unroll
            for (int nt = 0; nt < 8; nt++) {
                int n0 = nt * 8 + 2 * c4;
                float2 b2p = *(const float2*)&sb2[n0];
                float2 w3p = *(const float2*)&sW3[n0];
                float v0 = C[mt][nt][half * 2 + 0] + b2p.x;
                float v1 = C[mt][nt][half * 2 + 1] + b2p.y;
                acc = fmaf(fmaxf(v0, 0.0f), w3p.x, acc);
                acc = fmaf(fmaxf(v1, 0.0f), w3p.y, acc);
            }
            acc += __shfl_xor_sync(0xffffffffu, acc, 1);
            acc += __shfl_xor_sync(0xffffffffu, acc, 2);
            int row = r4 + 8 * rs;
            int pr = __shfl_sync(0xffffffffu, p, row);
            if (c4 == 0 && base + row < cnt) out[pr] = acc + b3s;
        }
    }
}

extern "C" void kernel_launch(void* const* d_in, const int* in_sizes, int n_in,
                              void* d_out, int out_size) {
    const float* x    = (const float*)d_in[0];
    const float* emin = (const float*)d_in[1];
    const float* emax = (const float*)d_in[2];
    const float* W1   = (const float*)d_in[3];
    const float* b1   = (const float*)d_in[4];
    const float* W2   = (const float*)d_in[5];
    const float* b2   = (const float*)d_in[6];
    const float* W3   = (const float*)d_in[7];
    const float* b3   = (const float*)d_in[8];
    float* out = (float*)d_out;

    int n = in_sizes[0] / 3;
    int nblk = (n + TPB - 1) / TPB;

    k_route<<<nblk, TPB>>>(x, n);
    k_prefix<<<1, 256>>>(nblk);
    k_scatter<<<nblk, TPB>>>(n);
    k_mlp<<<E * BPE, MTPB>>>(x, emin, emax, W1, b1, W2, b2, W3, b3, out);
}

// round 5
// speedup vs baseline: 4.5789x; 1.1525x over previous
#include <cuda_runtime.h>
#include <cuda_bf16.h>
#include <cstdint>

#define NMAX 524288
#define E 8
#define H 64
#define TPB 256
#define MTPB 256
#define BPE 37
#define NBLKMAX (NMAX / TPB)

// ---- scratch ----
__device__ int g_idx[NMAX];
__device__ int g_perm[NMAX];
__device__ int g_bh[NBLKMAX * E];
__device__ int g_counts[E];
__device__ int g_base[E];
__device__ int g_cursor[E];

// ================= helpers =================
__device__ __forceinline__ uint32_t packbf2(float lo, float hi) {
    uint32_t r;
    asm("cvt.rn.bf16x2.f32 %0, %1, %2;" : "=r"(r) : "f"(hi), "f"(lo));
    return r;
}
__device__ __forceinline__ float bflo_f(uint32_t w) { return __uint_as_float(w << 16); }
__device__ __forceinline__ float bfhi_f(uint32_t w) { return __uint_as_float(w & 0xffff0000u); }

__device__ __forceinline__ void mma16816(float* c, uint32_t a0, uint32_t a1,
                                         uint32_t a2, uint32_t a3,
                                         uint32_t b0, uint32_t b1) {
    asm volatile(
        "mma.sync.aligned.m16n8k16.row.col.f32.bf16.bf16.f32 "
        "{%0,%1,%2,%3}, {%4,%5,%6,%7}, {%8,%9}, {%0,%1,%2,%3};"
        : "+f"(c[0]), "+f"(c[1]), "+f"(c[2]), "+f"(c[3])
        : "r"(a0), "r"(a1), "r"(a2), "r"(a3), "r"(b0), "r"(b1));
}

// ================= sort kernels =================
__global__ void k_route(const float* __restrict__ x, int n) {
    __shared__ int hist[E];
    if (threadIdx.x < E) hist[threadIdx.x] = 0;
    __syncthreads();
    int i = blockIdx.x * TPB + threadIdx.x;
    if (i < n) {
        float u0 = fminf(fmaxf((x[3 * i + 0] + 1.0f) * 0.5f, 0.0f), 0.99f);
        float u1 = fminf(fmaxf((x[3 * i + 1] + 1.0f) * 0.5f, 0.0f), 0.99f);
        float u2 = fminf(fmaxf((x[3 * i + 2] + 1.0f) * 0.5f, 0.0f), 0.99f);
        int idx = (int)(u0 * 2.0f) + 2 * (int)(u1 * 2.0f) + 4 * (int)(u2 * 2.0f);
        g_idx[i] = idx;
        atomicAdd(&hist[idx], 1);
    }
    __syncthreads();
    if (threadIdx.x < E) g_bh[blockIdx.x * E + threadIdx.x] = hist[threadIdx.x];
}

__global__ void k_prefix(int nblk) {
    __shared__ int partial[256];
    int e = threadIdx.x % E;
    int c = threadIdx.x / E;
    int s = 0;
    for (int b = c; b < nblk; b += 32) s += g_bh[b * E + e];
    partial[threadIdx.x] = s;
    __syncthreads();
    if (threadIdx.x == 0) {
        int base = 0;
        for (int ee = 0; ee < E; ee++) {
            int tot = 0;
            for (int cc = 0; cc < 32; cc++) tot += partial[cc * E + ee];
            g_counts[ee] = tot;
            g_base[ee] = base;
            g_cursor[ee] = base;
            base += tot;
        }
    }
}

__global__ void k_scatter(int n) {
    __shared__ int hist[E], sbase[E], scur[E];
    int tid = threadIdx.x;
    if (tid < E) { hist[tid] = 0; scur[tid] = 0; }
    __syncthreads();
    int i = blockIdx.x * TPB + tid;
    int e = 0;
    if (i < n) {
        e = g_idx[i];
        atomicAdd(&hist[e], 1);
    }
    __syncthreads();
    if (tid < E) sbase[tid] = atomicAdd(&g_cursor[tid], hist[tid]);
    __syncthreads();
    if (i < n) {
        int r = atomicAdd(&scur[e], 1);
        g_perm[sbase[e] + r] = i;
    }
}

// ================= HMMA MLP =================
// Each warp: 32 points (M=32, 2 m-tiles), N=64 (8 n-tiles), K=64 (4 k-tiles),
// bf16 hi/lo 3-pass for fp32-grade precision. 2 CTAs/SM via reg cap.
__global__ void __launch_bounds__(MTPB, 2)
k_mlp(const float* __restrict__ x,
      const float* __restrict__ emin_g, const float* __restrict__ emax_g,
      const float* __restrict__ W1g, const float* __restrict__ b1g,
      const float* __restrict__ W2g, const float* __restrict__ b2g,
      const float* __restrict__ W3g, const float* __restrict__ b3g,
      float* __restrict__ out) {
    __shared__ uint2 sB[2][4][8][32];   // [hi/lo][ktile][ntile][lane] = (b0,b1)
    __shared__ float sW1[3][H];
    __shared__ float sb1[H], sb2[H], sW3[H];
    __shared__ float sext[6];
    __shared__ float sb3v;

    const int tid = threadIdx.x;
    const int e  = blockIdx.x / BPE;
    const int jb = blockIdx.x % BPE;

    // ---- stage small weights ----
    for (int t = tid; t < 3 * H; t += MTPB) sW1[t / H][t % H] = W1g[e * 3 * H + t];
    for (int t = tid; t < H; t += MTPB) {
        sb1[t] = b1g[e * H + t];
        sb2[t] = b2g[e * H + t];
        sW3[t] = W3g[e * H + t];
    }
    if (tid < 3) {
        sext[tid]     = emin_g[e * 3 + tid];
        sext[tid + 3] = emax_g[e * 3 + tid];
    }
    if (tid == 0) sb3v = b3g[e];

    // ---- stage B fragments (W2 as bf16 hi/lo) in mma register order ----
    {
        const float* w2e = W2g + e * H * H;
        for (int it = 0; it < 4; it++) {
            int idx = tid + it * MTPB;
            int kt = idx >> 8;
            int nt = (idx >> 5) & 7;
            int ln = idx & 31;
            int k0 = kt * 16 + 2 * (ln & 3);
            int n  = nt * 8 + (ln >> 2);
            float v00 = w2e[(k0)     * H + n];
            float v01 = w2e[(k0 + 1) * H + n];
            float v10 = w2e[(k0 + 8) * H + n];
            float v11 = w2e[(k0 + 9) * H + n];
            uint32_t h0 = packbf2(v00, v01);
            uint32_t h1 = packbf2(v10, v11);
            uint32_t l0 = packbf2(v00 - bflo_f(h0), v01 - bfhi_f(h0));
            uint32_t l1 = packbf2(v10 - bflo_f(h1), v11 - bfhi_f(h1));
            sB[0][kt][nt][ln] = make_uint2(h0, h1);
            sB[1][kt][nt][ln] = make_uint2(l0, l1);
        }
    }
    __syncthreads();

    const int lane = tid & 31;
    const int wid  = tid >> 5;
    const int c4 = lane & 3;
    const int r4 = lane >> 2;
    const int cnt = g_counts[e];
    const int gb  = g_base[e];
    const float e0 = sext[0], e1 = sext[1], e2 = sext[2];
    const float f0 = sext[3], f1 = sext[4], f2 = sext[5];
    const float b3s = sb3v;

    for (int base = (jb * 8 + wid) * 32; base < cnt; base += BPE * 8 * 32) {
        int slot = base + lane;
        int p = g_perm[gb + min(slot, cnt - 1)];
        float xn0 = -1.0f + 2.0f * (x[3 * p + 0] - e0) / (f0 - e0);
        float xn1 = -1.0f + 2.0f * (x[3 * p + 1] - e1) / (f1 - e1);
        float xn2 = -1.0f + 2.0f * (x[3 * p + 2] - e2) / (f2 - e2);

        float C[2][8][4];
#pragma unroll
        for (int mt = 0; mt < 2; mt++)
#pragma unroll
            for (int nt = 0; nt < 8; nt++)
#pragma unroll
                for (int q = 0; q < 4; q++) C[mt][nt][q] = 0.0f;

#pragma unroll
        for (int kt = 0; kt < 4; kt++) {
            int k0 = kt * 16 + 2 * c4;
            float2 b1L = *(const float2*)&sb1[k0];
            float2 b1H = *(const float2*)&sb1[k0 + 8];
            float2 wL0 = *(const float2*)&sW1[0][k0];
            float2 wL1 = *(const float2*)&sW1[1][k0];
            float2 wL2 = *(const float2*)&sW1[2][k0];
            float2 wH0 = *(const float2*)&sW1[0][k0 + 8];
            float2 wH1 = *(const float2*)&sW1[1][k0 + 8];
            float2 wH2 = *(const float2*)&sW1[2][k0 + 8];

            uint32_t ahi[2][4], alo[2][4];
#pragma unroll
            for (int rs = 0; rs < 4; rs++) {
                int src = r4 + 8 * rs;
                float a = __shfl_sync(0xffffffffu, xn0, src);
                float b = __shfl_sync(0xffffffffu, xn1, src);
                float c = __shfl_sync(0xffffffffu, xn2, src);
                float hx = fmaxf(fmaf(a, wL0.x, fmaf(b, wL1.x, fmaf(c, wL2.x, b1L.x))), 0.0f);
                float hy = fmaxf(fmaf(a, wL0.y, fmaf(b, wL1.y, fmaf(c, wL2.y, b1L.y))), 0.0f);
                float gx = fmaxf(fmaf(a, wH0.x, fmaf(b, wH1.x, fmaf(c, wH2.x, b1H.x))), 0.0f);
                float gy = fmaxf(fmaf(a, wH0.y, fmaf(b, wH1.y, fmaf(c, wH2.y, b1H.y))), 0.0f);
                uint32_t ph  = packbf2(hx, hy);
                uint32_t pg  = packbf2(gx, gy);
                uint32_t pl  = packbf2(hx - bflo_f(ph), hy - bfhi_f(ph));
                uint32_t pgl = packbf2(gx - bflo_f(pg), gy - bfhi_f(pg));
                int mt = rs >> 1, half = rs & 1;
                ahi[mt][half]     = ph;
                ahi[mt][2 + half] = pg;
                alo[mt][half]     = pl;
                alo[mt][2 + half] = pgl;
            }

#pragma unroll
            for (int nt = 0; nt < 8; nt++) {
                uint2 bh = sB[0][kt][nt][lane];
                uint2 bl = sB[1][kt][nt][lane];
#pragma unroll
                for (int mt = 0; mt < 2; mt++) {
                    mma16816(C[mt][nt], ahi[mt][0], ahi[mt][1], ahi[mt][2], ahi[mt][3], bh.x, bh.y);
                    mma16816(C[mt][nt], ahi[mt][0], ahi[mt][1], ahi[mt][2], ahi[mt][3], bl.x, bl.y);
                    mma16816(C[mt][nt], alo[mt][0], alo[mt][1], alo[mt][2], alo[mt][3], bh.x, bh.y);
                }
            }
        }

        // ---- epilogue: bias + relu + dot(W3), reduce across the 4-lane group ----
#pragma unroll
        for (int rs = 0; rs < 4; rs++) {
            int mt = rs >> 1, half = rs & 1;
            float acc = 0.0f;
#pragma unroll
            for (int nt = 0; nt < 8; nt++) {
                int n0 = nt * 8 + 2 * c4;
                float2 b2p = *(const float2*)&sb2[n0];
                float2 w3p = *(const float2*)&sW3[n0];
                float v0 = C[mt][nt][half * 2 + 0] + b2p.x;
                float v1 = C[mt][nt][half * 2 + 1] + b2p.y;
                acc = fmaf(fmaxf(v0, 0.0f), w3p.x, acc);
                acc = fmaf(fmaxf(v1, 0.0f), w3p.y, acc);
            }
            acc += __shfl_xor_sync(0xffffffffu, acc, 1);
            acc += __shfl_xor_sync(0xffffffffu, acc, 2);
            int row = r4 + 8 * rs;
            int pr = __shfl_sync(0xffffffffu, p, row);
            if (c4 == 0 && base + row < cnt) out[pr] = acc + b3s;
        }
    }
}

extern "C" void kernel_launch(void* const* d_in, const int* in_sizes, int n_in,
                              void* d_out, int out_size) {
    const float* x    = (const float*)d_in[0];
    const float* emin = (const float*)d_in[1];
    const float* emax = (const float*)d_in[2];
    const float* W1   = (const float*)d_in[3];
    const float* b1   = (const float*)d_in[4];
    const float* W2   = (const float*)d_in[5];
    const float* b2   = (const float*)d_in[6];
    const float* W3   = (const float*)d_in[7];
    const float* b3   = (const float*)d_in[8];
    float* out = (float*)d_out;

    int n = in_sizes[0] / 3;
    int nblk = (n + TPB - 1) / TPB;

    k_route<<<nblk, TPB>>>(x, n);
    k_prefix<<<1, 256>>>(nblk);
    k_scatter<<<nblk, TPB>>>(n);
    k_mlp<<<E * BPE, MTPB>>>(x, emin, emax, W1, b1, W2, b2, W3, b3, out);
}

// round 6
// speedup vs baseline: 5.4027x; 1.1799x over previous
#include <cuda_runtime.h>
#include <cuda_bf16.h>
#include <cuda_fp16.h>
#include <cstdint>

#define NMAX 524288
#define E 8
#define H 64
#define TPB 256
#define MTPB 256
#define BPE 37
#define NBLKMAX (NMAX / TPB)

// ---- scratch ----
__device__ int g_idx[NMAX];
__device__ int g_perm[NMAX];
__device__ int g_bh[NBLKMAX * E];
__device__ int g_counts[E];
__device__ int g_base[E];
__device__ int g_cursor[E];

// ================= helpers =================
// pack two f32 -> f16x2 word: low half = lo arg, high half = hi arg
__device__ __forceinline__ uint32_t packh2(float lo, float hi) {
    uint32_t r;
    asm("cvt.rn.f16x2.f32 %0, %1, %2;" : "=r"(r) : "f"(hi), "f"(lo));
    return r;
}

__device__ __forceinline__ void mma16816(float* c, uint32_t a0, uint32_t a1,
                                         uint32_t a2, uint32_t a3,
                                         uint32_t b0, uint32_t b1) {
    asm volatile(
        "mma.sync.aligned.m16n8k16.row.col.f32.f16.f16.f32 "
        "{%0,%1,%2,%3}, {%4,%5,%6,%7}, {%8,%9}, {%0,%1,%2,%3};"
        : "+f"(c[0]), "+f"(c[1]), "+f"(c[2]), "+f"(c[3])
        : "r"(a0), "r"(a1), "r"(a2), "r"(a3), "r"(b0), "r"(b1));
}

// ================= sort kernels =================
__global__ void k_route(const float* __restrict__ x, int n) {
    __shared__ int hist[E];
    if (threadIdx.x < E) hist[threadIdx.x] = 0;
    __syncthreads();
    int i = blockIdx.x * TPB + threadIdx.x;
    if (i < n) {
        float u0 = fminf(fmaxf((x[3 * i + 0] + 1.0f) * 0.5f, 0.0f), 0.99f);
        float u1 = fminf(fmaxf((x[3 * i + 1] + 1.0f) * 0.5f, 0.0f), 0.99f);
        float u2 = fminf(fmaxf((x[3 * i + 2] + 1.0f) * 0.5f, 0.0f), 0.99f);
        int idx = (int)(u0 * 2.0f) + 2 * (int)(u1 * 2.0f) + 4 * (int)(u2 * 2.0f);
        g_idx[i] = idx;
        atomicAdd(&hist[idx], 1);
    }
    __syncthreads();
    if (threadIdx.x < E) g_bh[blockIdx.x * E + threadIdx.x] = hist[threadIdx.x];
}

__global__ void k_prefix(int nblk) {
    __shared__ int partial[256];
    int e = threadIdx.x % E;
    int c = threadIdx.x / E;
    int s = 0;
    for (int b = c; b < nblk; b += 32) s += g_bh[b * E + e];
    partial[threadIdx.x] = s;
    __syncthreads();
    if (threadIdx.x == 0) {
        int base = 0;
        for (int ee = 0; ee < E; ee++) {
            int tot = 0;
            for (int cc = 0; cc < 32; cc++) tot += partial[cc * E + ee];
            g_counts[ee] = tot;
            g_base[ee] = base;
            g_cursor[ee] = base;
            base += tot;
        }
    }
}

__global__ void k_scatter(int n) {
    __shared__ int hist[E], sbase[E], scur[E];
    int tid = threadIdx.x;
    if (tid < E) { hist[tid] = 0; scur[tid] = 0; }
    __syncthreads();
    int i = blockIdx.x * TPB + tid;
    int e = 0;
    if (i < n) {
        e = g_idx[i];
        atomicAdd(&hist[e], 1);
    }
    __syncthreads();
    if (tid < E) sbase[tid] = atomicAdd(&g_cursor[tid], hist[tid]);
    __syncthreads();
    if (i < n) {
        int r = atomicAdd(&scur[e], 1);
        g_perm[sbase[e] + r] = i;
    }
}

// ================= HMMA MLP =================
// Each warp: 32 points (M=32, 2 m-tiles), N=64 (8 n-tiles), K=64 (4 k-tiles).
// fp16 2-pass: A = fp16(h), B = b_hi + b_lo (fp16 each). Dropped term ~2^-11.
__global__ void __launch_bounds__(MTPB, 2)
k_mlp(const float* __restrict__ x,
      const float* __restrict__ emin_g, const float* __restrict__ emax_g,
      const float* __restrict__ W1g, const float* __restrict__ b1g,
      const float* __restrict__ W2g, const float* __restrict__ b2g,
      const float* __restrict__ W3g, const float* __restrict__ b3g,
      float* __restrict__ out) {
    __shared__ uint2 sB[2][4][8][32];   // [hi/lo][ktile][ntile][lane] = (b0,b1)
    __shared__ float sW1[3][H];
    __shared__ float sb1[H], sb2[H], sW3[H];
    __shared__ float sext[6];
    __shared__ float sb3v;

    const int tid = threadIdx.x;
    const int e  = blockIdx.x / BPE;
    const int jb = blockIdx.x % BPE;

    // ---- stage small weights ----
    for (int t = tid; t < 3 * H; t += MTPB) sW1[t / H][t % H] = W1g[e * 3 * H + t];
    for (int t = tid; t < H; t += MTPB) {
        sb1[t] = b1g[e * H + t];
        sb2[t] = b2g[e * H + t];
        sW3[t] = W3g[e * H + t];
    }
    if (tid < 3) {
        sext[tid]     = emin_g[e * 3 + tid];
        sext[tid + 3] = emax_g[e * 3 + tid];
    }
    if (tid == 0) sb3v = b3g[e];

    // ---- stage B fragments (W2 as fp16 hi/lo) in mma register order ----
    {
        const float* w2e = W2g + e * H * H;
        for (int it = 0; it < 4; it++) {
            int idx = tid + it * MTPB;
            int kt = idx >> 8;
            int nt = (idx >> 5) & 7;
            int ln = idx & 31;
            int k0 = kt * 16 + 2 * (ln & 3);
            int n  = nt * 8 + (ln >> 2);
            float v00 = w2e[(k0)     * H + n];
            float v01 = w2e[(k0 + 1) * H + n];
            float v10 = w2e[(k0 + 8) * H + n];
            float v11 = w2e[(k0 + 9) * H + n];
            float h00 = __half2float(__float2half_rn(v00));
            float h01 = __half2float(__float2half_rn(v01));
            float h10 = __half2float(__float2half_rn(v10));
            float h11 = __half2float(__float2half_rn(v11));
            sB[0][kt][nt][ln] = make_uint2(packh2(h00, h01), packh2(h10, h11));
            sB[1][kt][nt][ln] = make_uint2(packh2(v00 - h00, v01 - h01),
                                           packh2(v10 - h10, v11 - h11));
        }
    }
    __syncthreads();

    const int lane = tid & 31;
    const int wid  = tid >> 5;
    const int c4 = lane & 3;
    const int r4 = lane >> 2;
    const int cnt = g_counts[e];
    const int gb  = g_base[e];
    const float e0 = sext[0], e1 = sext[1], e2 = sext[2];
    const float f0 = sext[3], f1 = sext[4], f2 = sext[5];
    const float b3s = sb3v;

    for (int base = (jb * 8 + wid) * 32; base < cnt; base += BPE * 8 * 32) {
        int slot = base + lane;
        int p = g_perm[gb + min(slot, cnt - 1)];
        float xn0 = -1.0f + 2.0f * (x[3 * p + 0] - e0) / (f0 - e0);
        float xn1 = -1.0f + 2.0f * (x[3 * p + 1] - e1) / (f1 - e1);
        float xn2 = -1.0f + 2.0f * (x[3 * p + 2] - e2) / (f2 - e2);

        float C[2][8][4];
#pragma unroll
        for (int mt = 0; mt < 2; mt++)
#pragma unroll
            for (int nt = 0; nt < 8; nt++)
#pragma unroll
                for (int q = 0; q < 4; q++) C[mt][nt][q] = 0.0f;

#pragma unroll
        for (int kt = 0; kt < 4; kt++) {
            int k0 = kt * 16 + 2 * c4;
            float2 b1L = *(const float2*)&sb1[k0];
            float2 b1H = *(const float2*)&sb1[k0 + 8];
            float2 wL0 = *(const float2*)&sW1[0][k0];
            float2 wL1 = *(const float2*)&sW1[1][k0];
            float2 wL2 = *(const float2*)&sW1[2][k0];
            float2 wH0 = *(const float2*)&sW1[0][k0 + 8];
            float2 wH1 = *(const float2*)&sW1[1][k0 + 8];
            float2 wH2 = *(const float2*)&sW1[2][k0 + 8];

            uint32_t af[2][4];
#pragma unroll
            for (int rs = 0; rs < 4; rs++) {
                int src = r4 + 8 * rs;
                float a = __shfl_sync(0xffffffffu, xn0, src);
                float b = __shfl_sync(0xffffffffu, xn1, src);
                float c = __shfl_sync(0xffffffffu, xn2, src);
                float hx = fmaxf(fmaf(a, wL0.x, fmaf(b, wL1.x, fmaf(c, wL2.x, b1L.x))), 0.0f);
                float hy = fmaxf(fmaf(a, wL0.y, fmaf(b, wL1.y, fmaf(c, wL2.y, b1L.y))), 0.0f);
                float gx = fmaxf(fmaf(a, wH0.x, fmaf(b, wH1.x, fmaf(c, wH2.x, b1H.x))), 0.0f);
                float gy = fmaxf(fmaf(a, wH0.y, fmaf(b, wH1.y, fmaf(c, wH2.y, b1H.y))), 0.0f);
                int mt = rs >> 1, half = rs & 1;
                af[mt][half]     = packh2(hx, hy);
                af[mt][2 + half] = packh2(gx, gy);
            }

            // hoist all B fragments for this k-tile into registers
            uint2 bh[8], bl[8];
#pragma unroll
            for (int nt = 0; nt < 8; nt++) {
                bh[nt] = sB[0][kt][nt][lane];
                bl[nt] = sB[1][kt][nt][lane];
            }

            // pass 1 (b_hi), then pass 2 (b_lo): C[mt][nt] reuse distance = 16 MMAs
#pragma unroll
            for (int nt = 0; nt < 8; nt++) {
#pragma unroll
                for (int mt = 0; mt < 2; mt++)
                    mma16816(C[mt][nt], af[mt][0], af[mt][1], af[mt][2], af[mt][3],
                             bh[nt].x, bh[nt].y);
            }
#pragma unroll
            for (int nt = 0; nt < 8; nt++) {
#pragma unroll
                for (int mt = 0; mt < 2; mt++)
                    mma16816(C[mt][nt], af[mt][0], af[mt][1], af[mt][2], af[mt][3],
                             bl[nt].x, bl[nt].y);
            }
        }

        // ---- epilogue: bias + relu + dot(W3), reduce across the 4-lane group ----
#pragma unroll
        for (int rs = 0; rs < 4; rs++) {
            int mt = rs >> 1, half = rs & 1;
            float acc = 0.0f;
#pragma unroll
            for (int nt = 0; nt < 8; nt++) {
                int n0 = nt * 8 + 2 * c4;
                float2 b2p = *(const float2*)&sb2[n0];
                float2 w3p = *(const float2*)&sW3[n0];
                float v0 = C[mt][nt][half * 2 + 0] + b2p.x;
                float v1 = C[mt][nt][half * 2 + 1] + b2p.y;
                acc = fmaf(fmaxf(v0, 0.0f), w3p.x, acc);
                acc = fmaf(fmaxf(v1, 0.0f), w3p.y, acc);
            }
            acc += __shfl_xor_sync(0xffffffffu, acc, 1);
            acc += __shfl_xor_sync(0xffffffffu, acc, 2);
            int row = r4 + 8 * rs;
            int pr = __shfl_sync(0xffffffffu, p, row);
            if (c4 == 0 && base + row < cnt) out[pr] = acc + b3s;
        }
    }
}

extern "C" void kernel_launch(void* const* d_in, const int* in_sizes, int n_in,
                              void* d_out, int out_size) {
    const float* x    = (const float*)d_in[0];
    const float* emin = (const float*)d_in[1];
    const float* emax = (const float*)d_in[2];
    const float* W1   = (const float*)d_in[3];
    const float* b1   = (const float*)d_in[4];
    const float* W2   = (const float*)d_in[5];
    const float* b2   = (const float*)d_in[6];
    const float* W3   = (const float*)d_in[7];
    const float* b3   = (const float*)d_in[8];
    float* out = (float*)d_out;

    int n = in_sizes[0] / 3;
    int nblk = (n + TPB - 1) / TPB;

    k_route<<<nblk, TPB>>>(x, n);
    k_prefix<<<1, 256>>>(nblk);
    k_scatter<<<nblk, TPB>>>(n);
    k_mlp<<<E * BPE, MTPB>>>(x, emin, emax, W1, b1, W2, b2, W3, b3, out);
}